// round 15
// baseline (speedup 1.0000x reference)
#include <cuda_runtime.h>
#include <cuda_fp16.h>
#include <cstdint>

#define NSER 8
#define NLAY 4
#define HDIM 256
#define TILE_M 64
#define THREADS 256

// ---- smem layout (byte offsets from 1024-aligned base) ----
#define SM_A      0                     // 64x256 fp16 SW128 blocked atoms (32768)
#define SM_BB     32768                 // B chunk double buffer: 2 x 32768
#define SM_BIAS   98304                 // ALL 4 layer biases as f16: 4 x 512
#define SM_W0     100352                // 3072 (f32)
#define SM_B0     103424                // 1024 (f32)
#define SM_RED    104448                // 256 floats (1024)
#define SM_CO     105472                // staged coords 64x3 f32 (768)
#define SMEM_BYTES (106240 + 1024)

// Pre-swizzled fp16 weight tiles: [s*4+l] tiles, each 256(out j) x 256(in k).
// Image = 16 contiguous 32KB chunks per series (4 per layer).
__device__ __half g_Bw[(size_t)NSER * NLAY * HDIM * HDIM];

__device__ __forceinline__ uint32_t swz(uint32_t o) { return o ^ ((o >> 3) & 0x70); }

__device__ __forceinline__ uint32_t b_off(int j, int k) {
    uint32_t o = ((uint32_t)(j >> 3) + (uint32_t)(k >> 6) * 32u) * 1024u
               + (uint32_t)(j & 7) * 128u + (uint32_t)(k & 63) * 2u;
    return swz(o);
}

__device__ __forceinline__ uint32_t s2u(const void* p) {
    uint32_t a;
    asm("{ .reg .u64 t; cvta.to.shared.u64 t, %1; cvt.u32.u64 %0, t; }" : "=r"(a) : "l"(p));
    return a;
}

// final-layer softplus: 1 MUFU (ex2) + f32 deg-5 poly for ln(1+u) (err<=1e-5)
__device__ __forceinline__ float softplus_poly(float x) {
    float u;
    asm("ex2.approx.ftz.f32 %0, %1;" : "=f"(u)
        : "f"(fabsf(x) * -1.4426950408889634f));
    float p = fmaf(0.03215845f, u, -0.13606275f);
    p = fmaf(p, u, 0.28947478f);
    p = fmaf(p, u, -0.49190896f);
    p = fmaf(p, u, 0.99949556f);
    return fmaxf(x, 0.f) + p * u;
}

// half2-native softplus: v already holds x (f16x2).
// softplus(x) = max(x,0) + ln(1+u), u = 2^(-|x|*log2e); deg-5 poly in HFMA2.
__device__ __forceinline__ __half2 sp2p(__half2 v) {
    const __half2 nL2E = __floats2half2_rn(-1.4426950408889634f,
                                           -1.4426950408889634f);
    __half2 t = __hmul2(__habs2(v), nL2E);
    __half2 u;
    asm("ex2.approx.f16x2 %0, %1;"
        : "=r"(*(uint32_t*)&u) : "r"(*(uint32_t*)&t));
    const __half2 c5 = __floats2half2_rn( 0.03215845f,  0.03215845f);
    const __half2 c4 = __floats2half2_rn(-0.13606275f, -0.13606275f);
    const __half2 c3 = __floats2half2_rn( 0.28947478f,  0.28947478f);
    const __half2 c2 = __floats2half2_rn(-0.49190896f, -0.49190896f);
    const __half2 c1 = __floats2half2_rn( 0.99949556f,  0.99949556f);
    __half2 p = __hfma2(c5, u, c4);
    p = __hfma2(p, u, c3);
    p = __hfma2(p, u, c2);
    p = __hfma2(p, u, c1);
    __half2 relu = __hmax2(v, __floats2half2_rn(0.f, 0.f));
    return __hfma2(p, u, relu);
}

// ---- prep: fp32 Wh[s][l][k][j] (k=in, j=out) -> fp16 pre-swizzled B images ----
__global__ void prep_weights(const float* __restrict__ Wh) {
    int idx = blockIdx.x * blockDim.x + threadIdx.x;
    if (idx >= NSER * NLAY * HDIM * HDIM) return;
    int t = idx >> 16;
    int r = idx & 0xFFFF;
    int k = r >> 8;
    int j = r & 0xFF;
    float w = Wh[((size_t)t << 16) + (k << 8) + j];
    char* base = (char*)g_Bw + (size_t)t * 131072;
    *(__half*)(base + b_off(j, k)) = __float2half_rn(w);
}

__device__ __forceinline__ void ldsm_x4(uint32_t& r0, uint32_t& r1, uint32_t& r2,
                                        uint32_t& r3, uint32_t a) {
    asm volatile("ldmatrix.sync.aligned.m8n8.x4.shared.b16 {%0,%1,%2,%3}, [%4];"
                 : "=r"(r0), "=r"(r1), "=r"(r2), "=r"(r3) : "r"(a));
}
__device__ __forceinline__ void mma16816(float* c, uint32_t a0, uint32_t a1,
                                         uint32_t a2, uint32_t a3,
                                         uint32_t b0, uint32_t b1) {
    asm volatile(
        "mma.sync.aligned.m16n8k16.row.col.f32.f16.f16.f32 "
        "{%0,%1,%2,%3}, {%4,%5,%6,%7}, {%8,%9}, {%0,%1,%2,%3};"
        : "+f"(c[0]), "+f"(c[1]), "+f"(c[2]), "+f"(c[3])
        : "r"(a0), "r"(a1), "r"(a2), "r"(a3), "r"(b0), "r"(b1));
}

__device__ __forceinline__ void cp16(uint32_t saddr, const void* g) {
    asm volatile("cp.async.cg.shared.global [%0], [%1], 16;"
                 :: "r"(saddr), "l"(g) : "memory");
}
__device__ __forceinline__ void cp_commit() {
    asm volatile("cp.async.commit_group;" ::: "memory");
}
__device__ __forceinline__ void cp_wait1() {
    asm volatile("cp.async.wait_group 1;" ::: "memory");
}
__device__ __forceinline__ void cp_wait0() {
    asm volatile("cp.async.wait_group 0;" ::: "memory");
}

// copy one 32KB chunk (64 k-cols of B) by 256 threads: 8 x 16B per thread
__device__ __forceinline__ void issue_chunk(uint32_t sb, uint32_t bufoff,
                                            const char* g, int tid) {
    uint32_t d = sb + bufoff + (uint32_t)tid * 16u;
    #pragma unroll
    for (int i = 0; i < 8; i++)
        cp16(d + (uint32_t)i * 4096u, g + (size_t)tid * 16 + (size_t)i * 4096);
    cp_commit();
}

// one quarter-k of the layer MMA: 4 k-steps of 16 against the chunk at bufoff
__device__ __forceinline__ void mma_chunk(uint32_t sb, const uint32_t* a_rel,
    uint32_t a_xor, int akoff, uint32_t b_rel0, int bkoff, uint32_t b_xor,
    uint32_t bufoff, int kq, float* acc)
{
    #pragma unroll
    for (int kss = 0; kss < 4; kss++) {
        uint32_t af[8];
        const int ka = kq * 64 + kss * 16 + akoff;         // global k for A
        const uint32_t aterm = (uint32_t)((ka >> 6) * 8192)
                             + ((uint32_t)((ka & 63) * 2) ^ a_xor);
        ldsm_x4(af[0], af[1], af[2], af[3], sb + a_rel[0] + aterm);
        ldsm_x4(af[4], af[5], af[6], af[7], sb + a_rel[1] + aterm);
        const int kb = kss * 16 + bkoff;                   // chunk-local k (<64)
        uint32_t baddr = sb + bufoff + b_rel0
                       + ((uint32_t)(kb * 2) ^ b_xor);
        #pragma unroll
        for (int nf2 = 0; nf2 < 4; nf2++) {
            uint32_t br0, br1, br2, br3;
            ldsm_x4(br0, br1, br2, br3, baddr);
            baddr += 2048;
            mma16816(&acc[(nf2 * 2) * 4],         af[0], af[1], af[2], af[3], br0, br1);
            mma16816(&acc[(nf2 * 2 + 1) * 4],     af[0], af[1], af[2], af[3], br2, br3);
            mma16816(&acc[(8 + nf2 * 2) * 4],     af[4], af[5], af[6], af[7], br0, br1);
            mma16816(&acc[(8 + nf2 * 2 + 1) * 4], af[4], af[5], af[6], af[7], br2, br3);
        }
    }
}

__global__ void __launch_bounds__(THREADS, 2)
mlp_kernel(const float* __restrict__ coords,
           const float* __restrict__ W0,
           const float* __restrict__ b0,
           const float* __restrict__ bh,
           const float* __restrict__ Wout,
           const float* __restrict__ bout,
           float* __restrict__ out,
           int Ntot, int ntiles, int nslots)
{
    extern __shared__ char smem_raw[];
    char* sm = (char*)(((uintptr_t)smem_raw + 1023) & ~(uintptr_t)1023);
    const uint32_t sb = s2u(sm);
    const int tid = threadIdx.x;
    const int s    = blockIdx.x & 7;        // series pinned to this CTA
    const int slot = blockIdx.x >> 3;       // tile-stride slot

    const int wid = tid >> 5, ln = tid & 31;
    const int wm = wid & 1;                 // 2 M-tiles of 32 rows
    const int wn = wid >> 1;                // 4 N-tiles of 64 cols

    const char* tile_base = (const char*)(g_Bw + ((size_t)(s * NLAY) << 16));

    // ---- one-time prologue: chunk 0 + stage W0/b0 + biases (as f16) ----
    issue_chunk(sb, SM_BB, tile_base, tid);
    {
        const float* w0g = W0 + (size_t)s * 3 * HDIM;
        #pragma unroll
        for (int i = tid; i < 3 * HDIM; i += THREADS)
            ((float*)(sm + SM_W0))[i] = w0g[i];
        ((float*)(sm + SM_B0))[tid] = b0[(size_t)s * HDIM + tid];
        #pragma unroll
        for (int lj = 0; lj < NLAY; lj++)
            ((__half*)(sm + SM_BIAS + lj * 512))[tid] =
                __float2half_rn(bh[(size_t)(s * NLAY + lj) * HDIM + tid]);
    }

    // ---- per-lane fragment addressing (proven forms) ----
    uint32_t a_rel[2];
    #pragma unroll
    for (int mf = 0; mf < 2; mf++) {
        int m = wm * 32 + mf * 16 + (ln & 15);
        a_rel[mf] = (uint32_t)(SM_A + (m >> 3) * 1024 + (m & 7) * 128);
    }
    const uint32_t a_xor = (uint32_t)((ln & 7) * 16);
    const int akoff = (ln & 16) ? 8 : 0;
    const uint32_t b_rel0 = (uint32_t)(wn * 8192 + (ln & 7) * 128
                                       + ((ln & 16) ? 1024 : 0));
    const uint32_t b_xor = (uint32_t)((ln & 7) * 16);
    const int bkoff = (ln & 8) ? 8 : 0;

    const int eml[2] = { wm * 32 + 0 * 16 + (ln >> 2),
                         wm * 32 + 1 * 16 + (ln >> 2) };

    // layer-0 lane constants: thread = 8 rows (tr) x 8 cols (tj)
    const int tj = tid & 31;                 // col group: j = tj*8 .. tj*8+7
    const int tr = tid >> 5;                 // row group: m = tr*8 .. tr*8+7
    const uint32_t a0base = (uint32_t)(tr * 1024 + (tj >> 3) * 8192);
    const uint32_t jlow2 = (uint32_t)(((tj & 7) * 8) * 2);  // (j&63)*2 for c=0

    __syncthreads();   // staging visible (chunk 0 still in flight)

    for (int t = slot; t < ntiles; t += nslots) {
        const int base = t * TILE_M;

        // ---- stage coords for this tile (64 rows x 3 f32) ----
        if (tid < 192) {
            size_t gi = (size_t)base * 3 + tid;
            ((float*)(sm + SM_CO))[tid] =
                (gi < (size_t)Ntot * 3) ? coords[gi] : 0.f;
        }
        __syncthreads();

        // ---- layer 0: regs-resident W0 slice; 8 rows x 8 cols per thread ----
        {
            const float* sw0 = (const float*)(sm + SM_W0);
            const float* sb0 = (const float*)(sm + SM_B0);
            const float* co  = (const float*)(sm + SM_CO);
            const int j0 = tj * 8;
            float4 wa0 = *(const float4*)(sw0 + j0);
            float4 wa1 = *(const float4*)(sw0 + j0 + 4);
            float4 wb0 = *(const float4*)(sw0 + 256 + j0);
            float4 wb1 = *(const float4*)(sw0 + 256 + j0 + 4);
            float4 wc0 = *(const float4*)(sw0 + 512 + j0);
            float4 wc1 = *(const float4*)(sw0 + 512 + j0 + 4);
            float4 bb0 = *(const float4*)(sb0 + j0);
            float4 bb1 = *(const float4*)(sb0 + j0 + 4);
            const float wa[8] = {wa0.x,wa0.y,wa0.z,wa0.w,wa1.x,wa1.y,wa1.z,wa1.w};
            const float wb[8] = {wb0.x,wb0.y,wb0.z,wb0.w,wb1.x,wb1.y,wb1.z,wb1.w};
            const float wc[8] = {wc0.x,wc0.y,wc0.z,wc0.w,wc1.x,wc1.y,wc1.z,wc1.w};
            const float bv[8] = {bb0.x,bb0.y,bb0.z,bb0.w,bb1.x,bb1.y,bb1.z,bb1.w};
            #pragma unroll
            for (int r = 0; r < 8; r++) {
                const int m = tr * 8 + r;
                const float c0 = co[m * 3], c1 = co[m * 3 + 1], c2 = co[m * 3 + 2];
                const uint32_t rowrel = a0base + (uint32_t)(r * 128);
                const uint32_t rxor = (uint32_t)(r * 16);
                #pragma unroll
                for (int c = 0; c < 8; c += 2) {
                    float v0 = bv[c]   + c0 * wa[c]   + c1 * wb[c]   + c2 * wc[c];
                    float v1 = bv[c+1] + c0 * wa[c+1] + c1 * wb[c+1] + c2 * wc[c+1];
                    uint32_t rel = rowrel + ((jlow2 + (uint32_t)(c * 2)) ^ rxor);
                    *(__half2*)(sm + SM_A + rel) = sp2p(__floats2half2_rn(v0, v1));
                }
            }
        }

        float acc[64];

        #pragma unroll
        for (int l = 0; l < NLAY; l++) {
            #pragma unroll
            for (int i = 0; i < 64; i++) acc[i] = 0.f;

            #pragma unroll
            for (int kq = 0; kq < 4; kq++) {
                const int g = l * 4 + kq;              // chunk index within tile
                __syncthreads();                       // refill target reads done
                issue_chunk(sb, SM_BB + (uint32_t)(((g + 1) & 1) * 32768),
                            tile_base + (size_t)((g + 1) & 15) * 32768, tid);
                cp_wait1();                            // chunk g landed; g+1 flying
                __syncthreads();                       // chunk g visible CTA-wide
                mma_chunk(sb, a_rel, a_xor, akoff, b_rel0, bkoff, b_xor,
                          SM_BB + (uint32_t)((g & 1) * 32768), kq, acc);
            }
            __syncthreads();   // all mma reads of A done before A rewrite

            if (l < NLAY - 1) {
                // epilogue: f16 bias + half2 softplus -> A (in place)
                const __half2* sbh2 = (const __half2*)(sm + SM_BIAS + l * 512);
                #pragma unroll
                for (int mf = 0; mf < 2; mf++) {
                    const int mlo = eml[mf];
                    const uint32_t alo = (uint32_t)(SM_A + (mlo >> 3) * 1024
                                                    + (mlo & 7) * 128);
                    const uint32_t xlo = (uint32_t)((mlo & 7) * 16);
                    #pragma unroll
                    for (int nf = 0; nf < 8; nf++) {
                        const int n0 = wn * 64 + nf * 8 + (ln & 3) * 2;
                        const __half2 b2 = sbh2[n0 >> 1];
                        const float* a4 = &acc[(mf * 8 + nf) * 4];
                        const uint32_t kt = (uint32_t)((n0 >> 6) * 8192)
                                          + ((uint32_t)((n0 & 63) * 2) ^ xlo);
                        __half2 v01 = __hadd2(__floats2half2_rn(a4[0], a4[1]), b2);
                        __half2 v23 = __hadd2(__floats2half2_rn(a4[2], a4[3]), b2);
                        *(__half2*)(sm + alo + kt)        = sp2p(v01);
                        *(__half2*)(sm + alo + 1024 + kt) = sp2p(v23);
                    }
                }
                // next chunk's top __syncthreads orders these writes before reads
            } else {
                // final layer: f32 poly softplus * Wout, fused 256->1 dot
                const __half* sbhh = (const __half*)(sm + SM_BIAS + (NLAY - 1) * 512);
                const float* wog = Wout + (size_t)s * HDIM;
                float rsum[4];
                #pragma unroll
                for (int mf = 0; mf < 2; mf++) {
                    float lo = 0.f, hi = 0.f;
                    #pragma unroll
                    for (int nf = 0; nf < 8; nf++) {
                        const int n0 = wn * 64 + nf * 8 + (ln & 3) * 2;
                        const float bv0 = __half2float(sbhh[n0]);
                        const float bv1 = __half2float(sbhh[n0 + 1]);
                        const float w0v = __ldg(wog + n0), w1v = __ldg(wog + n0 + 1);
                        const float* a4 = &acc[(mf * 8 + nf) * 4];
                        lo += softplus_poly(a4[0] + bv0) * w0v
                            + softplus_poly(a4[1] + bv1) * w1v;
                        hi += softplus_poly(a4[2] + bv0) * w0v
                            + softplus_poly(a4[3] + bv1) * w1v;
                    }
                    rsum[mf * 2] = lo; rsum[mf * 2 + 1] = hi;
                }
                #pragma unroll
                for (int i = 0; i < 4; i++) {
                    rsum[i] += __shfl_xor_sync(0xffffffffu, rsum[i], 1);
                    rsum[i] += __shfl_xor_sync(0xffffffffu, rsum[i], 2);
                }
                float* red = (float*)(sm + SM_RED);
                if ((ln & 3) == 0) {
                    #pragma unroll
                    for (int mf = 0; mf < 2; mf++) {
                        const int mloL = eml[mf] & 63;
                        red[wn * 64 + mloL]     = rsum[mf * 2];
                        red[wn * 64 + mloL + 8] = rsum[mf * 2 + 1];
                    }
                }
                __syncthreads();
                if (tid < 64 && base + tid < Ntot) {
                    float v = red[tid] + red[64 + tid] + red[128 + tid]
                            + red[192 + tid] + __ldg(bout + s);
                    out[(size_t)(base + tid) * NSER + s] = v;
                }
            }
        }
    }
    cp_wait0();   // drain the phantom prefetch before exit
}

extern "C" void kernel_launch(void* const* d_in, const int* in_sizes, int n_in,
                              void* d_out, int out_size) {
    const float* coords = (const float*)d_in[0];
    const float* W0     = (const float*)d_in[1];
    const float* b0     = (const float*)d_in[2];
    const float* Wh     = (const float*)d_in[3];
    const float* bh     = (const float*)d_in[4];
    const float* Wout   = (const float*)d_in[5];
    const float* bout   = (const float*)d_in[6];
    const int Npts = in_sizes[0] / 3;

    cudaFuncSetAttribute(mlp_kernel, cudaFuncAttributeMaxDynamicSharedMemorySize,
                         SMEM_BYTES);

    const int wtotal = NSER * NLAY * HDIM * HDIM;
    prep_weights<<<(wtotal + 255) / 256, 256>>>(Wh);

    int nsm = 148;
    cudaDeviceGetAttribute(&nsm, cudaDevAttrMultiProcessorCount, 0);
    int grid = (2 * nsm) & ~7;              // 2 CTAs/SM, multiple of 8
    if (grid < 8) grid = 8;
    const int nslots = grid / 8;
    const int ntiles = (Npts + TILE_M - 1) / TILE_M;

    mlp_kernel<<<grid, THREADS, SMEM_BYTES>>>(coords, W0, b0, bh, Wout, bout,
                                              (float*)d_out, Npts, ntiles, nslots);

    long long need = (long long)Npts * NSER + (long long)Npts * 3;
    if ((long long)out_size >= need) {
        cudaMemcpyAsync((float*)d_out + (size_t)Npts * NSER, coords,
                        sizeof(float) * (size_t)Npts * 3,
                        cudaMemcpyDeviceToDevice, 0);
    }
}

// round 16
// speedup vs baseline: 1.0021x; 1.0021x over previous
#include <cuda_runtime.h>
#include <cuda_fp16.h>
#include <cstdint>

#define NSER 8
#define NLAY 4
#define HDIM 256
#define TILE_M 64
#define THREADS 256

// ---- smem layout (byte offsets from 1024-aligned base) ----
#define SM_A      0                     // 64x256 fp16 SW128 blocked atoms (32768)
#define SM_BB     32768                 // B chunk double buffer: 2 x 32768
#define SM_BIAS   98304                 // ALL 4 layer biases as f16: 4 x 512
#define SM_W0     100352                // 3072 (f32)
#define SM_B0     103424                // 1024 (f32)
#define SM_RED    104448                // 256 floats (1024)
#define SM_CO     105472                // staged coords 64x3 f32 (768)
#define SMEM_BYTES (106240 + 1024)

// Pre-swizzled fp16 weight tiles: [s*4+l] tiles, each 256(out j) x 256(in k).
// Image = 16 contiguous 32KB chunks per series (4 per layer).
__device__ __half g_Bw[(size_t)NSER * NLAY * HDIM * HDIM];

__device__ __forceinline__ uint32_t swz(uint32_t o) { return o ^ ((o >> 3) & 0x70); }

__device__ __forceinline__ uint32_t b_off(int j, int k) {
    uint32_t o = ((uint32_t)(j >> 3) + (uint32_t)(k >> 6) * 32u) * 1024u
               + (uint32_t)(j & 7) * 128u + (uint32_t)(k & 63) * 2u;
    return swz(o);
}

__device__ __forceinline__ uint32_t s2u(const void* p) {
    uint32_t a;
    asm("{ .reg .u64 t; cvta.to.shared.u64 t, %1; cvt.u32.u64 %0, t; }" : "=r"(a) : "l"(p));
    return a;
}

// final-layer softplus: 1 MUFU (ex2) + f32 deg-5 poly for ln(1+u) (err<=1e-5)
__device__ __forceinline__ float softplus_poly(float x) {
    float u;
    asm("ex2.approx.ftz.f32 %0, %1;" : "=f"(u)
        : "f"(fabsf(x) * -1.4426950408889634f));
    float p = fmaf(0.03215845f, u, -0.13606275f);
    p = fmaf(p, u, 0.28947478f);
    p = fmaf(p, u, -0.49190896f);
    p = fmaf(p, u, 0.99949556f);
    return fmaxf(x, 0.f) + p * u;
}

// half2-native softplus (round-15 proven)
__device__ __forceinline__ __half2 sp2p(__half2 v) {
    const __half2 nL2E = __floats2half2_rn(-1.4426950408889634f,
                                           -1.4426950408889634f);
    __half2 t = __hmul2(__habs2(v), nL2E);
    __half2 u;
    asm("ex2.approx.f16x2 %0, %1;"
        : "=r"(*(uint32_t*)&u) : "r"(*(uint32_t*)&t));
    const __half2 c5 = __floats2half2_rn( 0.03215845f,  0.03215845f);
    const __half2 c4 = __floats2half2_rn(-0.13606275f, -0.13606275f);
    const __half2 c3 = __floats2half2_rn( 0.28947478f,  0.28947478f);
    const __half2 c2 = __floats2half2_rn(-0.49190896f, -0.49190896f);
    const __half2 c1 = __floats2half2_rn( 0.99949556f,  0.99949556f);
    __half2 p = __hfma2(c5, u, c4);
    p = __hfma2(p, u, c3);
    p = __hfma2(p, u, c2);
    p = __hfma2(p, u, c1);
    __half2 relu = __hmax2(v, __floats2half2_rn(0.f, 0.f));
    return __hfma2(p, u, relu);
}

// ---- prep: fp32 Wh[s][l][k][j] (k=in, j=out) -> fp16 pre-swizzled B images ----
__global__ void prep_weights(const float* __restrict__ Wh) {
    int idx = blockIdx.x * blockDim.x + threadIdx.x;
    if (idx >= NSER * NLAY * HDIM * HDIM) return;
    int t = idx >> 16;
    int r = idx & 0xFFFF;
    int k = r >> 8;
    int j = r & 0xFF;
    float w = Wh[((size_t)t << 16) + (k << 8) + j];
    char* base = (char*)g_Bw + (size_t)t * 131072;
    *(__half*)(base + b_off(j, k)) = __float2half_rn(w);
}

__device__ __forceinline__ void ldsm_x4(uint32_t& r0, uint32_t& r1, uint32_t& r2,
                                        uint32_t& r3, uint32_t a) {
    asm volatile("ldmatrix.sync.aligned.m8n8.x4.shared.b16 {%0,%1,%2,%3}, [%4];"
                 : "=r"(r0), "=r"(r1), "=r"(r2), "=r"(r3) : "r"(a));
}
__device__ __forceinline__ void mma16816(float* c, uint32_t a0, uint32_t a1,
                                         uint32_t a2, uint32_t a3,
                                         uint32_t b0, uint32_t b1) {
    asm volatile(
        "mma.sync.aligned.m16n8k16.row.col.f32.f16.f16.f32 "
        "{%0,%1,%2,%3}, {%4,%5,%6,%7}, {%8,%9}, {%0,%1,%2,%3};"
        : "+f"(c[0]), "+f"(c[1]), "+f"(c[2]), "+f"(c[3])
        : "r"(a0), "r"(a1), "r"(a2), "r"(a3), "r"(b0), "r"(b1));
}

__device__ __forceinline__ void cp16(uint32_t saddr, const void* g) {
    asm volatile("cp.async.cg.shared.global [%0], [%1], 16;"
                 :: "r"(saddr), "l"(g) : "memory");
}
__device__ __forceinline__ void cp_commit() {
    asm volatile("cp.async.commit_group;" ::: "memory");
}
__device__ __forceinline__ void cp_wait1() {
    asm volatile("cp.async.wait_group 1;" ::: "memory");
}
__device__ __forceinline__ void cp_wait0() {
    asm volatile("cp.async.wait_group 0;" ::: "memory");
}

// copy one 32KB chunk (64 k-cols of B) by 256 threads: 8 x 16B per thread
__device__ __forceinline__ void issue_chunk(uint32_t sb, uint32_t bufoff,
                                            const char* g, int tid) {
    uint32_t d = sb + bufoff + (uint32_t)tid * 16u;
    #pragma unroll
    for (int i = 0; i < 8; i++)
        cp16(d + (uint32_t)i * 4096u, g + (size_t)tid * 16 + (size_t)i * 4096);
    cp_commit();
}

// one quarter-k of the layer MMA, software-pipelined:
// B fragments double-buffered across nf2; A fragments across kss.
__device__ __forceinline__ void mma_chunk(uint32_t sb, const uint32_t* a_rel,
    uint32_t a_xor, int akoff, uint32_t b_rel0, int bkoff, uint32_t b_xor,
    uint32_t bufoff, int kq, float* acc)
{
    uint32_t af[2][8];
    uint32_t br[2][4];

    // preload A for kss=0
    {
        const int ka = kq * 64 + akoff;
        const uint32_t aterm = (uint32_t)((ka >> 6) * 8192)
                             + ((uint32_t)((ka & 63) * 2) ^ a_xor);
        ldsm_x4(af[0][0], af[0][1], af[0][2], af[0][3], sb + a_rel[0] + aterm);
        ldsm_x4(af[0][4], af[0][5], af[0][6], af[0][7], sb + a_rel[1] + aterm);
    }

    #pragma unroll
    for (int kss = 0; kss < 4; kss++) {
        const int cur = kss & 1, nxt = cur ^ 1;
        const int kb = kss * 16 + bkoff;               // chunk-local k (<64)
        uint32_t baddr = sb + bufoff + b_rel0
                       + ((uint32_t)(kb * 2) ^ b_xor);
        // preload B for nf2=0
        ldsm_x4(br[0][0], br[0][1], br[0][2], br[0][3], baddr);

        #pragma unroll
        for (int nf2 = 0; nf2 < 4; nf2++) {
            const int bc = nf2 & 1;
            if (nf2 < 3) {
                // prefetch next B quartet
                ldsm_x4(br[bc ^ 1][0], br[bc ^ 1][1], br[bc ^ 1][2],
                        br[bc ^ 1][3], baddr + 2048);
            } else if (kss < 3) {
                // prefetch next kss's A fragments
                const int ka = kq * 64 + (kss + 1) * 16 + akoff;
                const uint32_t aterm = (uint32_t)((ka >> 6) * 8192)
                                     + ((uint32_t)((ka & 63) * 2) ^ a_xor);
                ldsm_x4(af[nxt][0], af[nxt][1], af[nxt][2], af[nxt][3],
                        sb + a_rel[0] + aterm);
                ldsm_x4(af[nxt][4], af[nxt][5], af[nxt][6], af[nxt][7],
                        sb + a_rel[1] + aterm);
            }
            mma16816(&acc[(nf2 * 2) * 4],
                     af[cur][0], af[cur][1], af[cur][2], af[cur][3],
                     br[bc][0], br[bc][1]);
            mma16816(&acc[(nf2 * 2 + 1) * 4],
                     af[cur][0], af[cur][1], af[cur][2], af[cur][3],
                     br[bc][2], br[bc][3]);
            mma16816(&acc[(8 + nf2 * 2) * 4],
                     af[cur][4], af[cur][5], af[cur][6], af[cur][7],
                     br[bc][0], br[bc][1]);
            mma16816(&acc[(8 + nf2 * 2 + 1) * 4],
                     af[cur][4], af[cur][5], af[cur][6], af[cur][7],
                     br[bc][2], br[bc][3]);
            baddr += 2048;
        }
    }
}

__global__ void __launch_bounds__(THREADS, 2)
mlp_kernel(const float* __restrict__ coords,
           const float* __restrict__ W0,
           const float* __restrict__ b0,
           const float* __restrict__ bh,
           const float* __restrict__ Wout,
           const float* __restrict__ bout,
           float* __restrict__ out,
           int Ntot, int ntiles, int nslots)
{
    extern __shared__ char smem_raw[];
    char* sm = (char*)(((uintptr_t)smem_raw + 1023) & ~(uintptr_t)1023);
    const uint32_t sb = s2u(sm);
    const int tid = threadIdx.x;
    const int s    = blockIdx.x & 7;        // series pinned to this CTA
    const int slot = blockIdx.x >> 3;       // tile-stride slot

    const int wid = tid >> 5, ln = tid & 31;
    const int wm = wid & 1;                 // 2 M-tiles of 32 rows
    const int wn = wid >> 1;                // 4 N-tiles of 64 cols

    const char* tile_base = (const char*)(g_Bw + ((size_t)(s * NLAY) << 16));

    // ---- one-time prologue: chunk 0 + stage W0/b0 + biases (as f16) ----
    issue_chunk(sb, SM_BB, tile_base, tid);
    {
        const float* w0g = W0 + (size_t)s * 3 * HDIM;
        #pragma unroll
        for (int i = tid; i < 3 * HDIM; i += THREADS)
            ((float*)(sm + SM_W0))[i] = w0g[i];
        ((float*)(sm + SM_B0))[tid] = b0[(size_t)s * HDIM + tid];
        #pragma unroll
        for (int lj = 0; lj < NLAY; lj++)
            ((__half*)(sm + SM_BIAS + lj * 512))[tid] =
                __float2half_rn(bh[(size_t)(s * NLAY + lj) * HDIM + tid]);
    }

    // ---- per-lane fragment addressing (proven forms) ----
    uint32_t a_rel[2];
    #pragma unroll
    for (int mf = 0; mf < 2; mf++) {
        int m = wm * 32 + mf * 16 + (ln & 15);
        a_rel[mf] = (uint32_t)(SM_A + (m >> 3) * 1024 + (m & 7) * 128);
    }
    const uint32_t a_xor = (uint32_t)((ln & 7) * 16);
    const int akoff = (ln & 16) ? 8 : 0;
    const uint32_t b_rel0 = (uint32_t)(wn * 8192 + (ln & 7) * 128
                                       + ((ln & 16) ? 1024 : 0));
    const uint32_t b_xor = (uint32_t)((ln & 7) * 16);
    const int bkoff = (ln & 8) ? 8 : 0;

    const int eml[2] = { wm * 32 + 0 * 16 + (ln >> 2),
                         wm * 32 + 1 * 16 + (ln >> 2) };

    // layer-0 lane constants: thread = 8 rows (tr) x 8 cols (tj)
    const int tj = tid & 31;                 // col group: j = tj*8 .. tj*8+7
    const int tr = tid >> 5;                 // row group: m = tr*8 .. tr*8+7
    const uint32_t a0base = (uint32_t)(tr * 1024 + (tj >> 3) * 8192);
    const uint32_t jlow2 = (uint32_t)(((tj & 7) * 8) * 2);  // (j&63)*2 for c=0

    __syncthreads();   // staging visible (chunk 0 still in flight)

    for (int t = slot; t < ntiles; t += nslots) {
        const int base = t * TILE_M;

        // ---- stage coords for this tile (64 rows x 3 f32) ----
        if (tid < 192) {
            size_t gi = (size_t)base * 3 + tid;
            ((float*)(sm + SM_CO))[tid] =
                (gi < (size_t)Ntot * 3) ? coords[gi] : 0.f;
        }
        __syncthreads();

        // ---- layer 0: regs-resident W0 slice; 8 rows x 8 cols per thread ----
        {
            const float* sw0 = (const float*)(sm + SM_W0);
            const float* sb0 = (const float*)(sm + SM_B0);
            const float* co  = (const float*)(sm + SM_CO);
            const int j0 = tj * 8;
            float4 wa0 = *(const float4*)(sw0 + j0);
            float4 wa1 = *(const float4*)(sw0 + j0 + 4);
            float4 wb0 = *(const float4*)(sw0 + 256 + j0);
            float4 wb1 = *(const float4*)(sw0 + 256 + j0 + 4);
            float4 wc0 = *(const float4*)(sw0 + 512 + j0);
            float4 wc1 = *(const float4*)(sw0 + 512 + j0 + 4);
            float4 bb0 = *(const float4*)(sb0 + j0);
            float4 bb1 = *(const float4*)(sb0 + j0 + 4);
            const float wa[8] = {wa0.x,wa0.y,wa0.z,wa0.w,wa1.x,wa1.y,wa1.z,wa1.w};
            const float wb[8] = {wb0.x,wb0.y,wb0.z,wb0.w,wb1.x,wb1.y,wb1.z,wb1.w};
            const float wc[8] = {wc0.x,wc0.y,wc0.z,wc0.w,wc1.x,wc1.y,wc1.z,wc1.w};
            const float bv[8] = {bb0.x,bb0.y,bb0.z,bb0.w,bb1.x,bb1.y,bb1.z,bb1.w};
            #pragma unroll
            for (int r = 0; r < 8; r++) {
                const int m = tr * 8 + r;
                const float c0 = co[m * 3], c1 = co[m * 3 + 1], c2 = co[m * 3 + 2];
                const uint32_t rowrel = a0base + (uint32_t)(r * 128);
                const uint32_t rxor = (uint32_t)(r * 16);
                #pragma unroll
                for (int c = 0; c < 8; c += 2) {
                    float v0 = bv[c]   + c0 * wa[c]   + c1 * wb[c]   + c2 * wc[c];
                    float v1 = bv[c+1] + c0 * wa[c+1] + c1 * wb[c+1] + c2 * wc[c+1];
                    uint32_t rel = rowrel + ((jlow2 + (uint32_t)(c * 2)) ^ rxor);
                    *(__half2*)(sm + SM_A + rel) = sp2p(__floats2half2_rn(v0, v1));
                }
            }
        }

        float acc[64];

        #pragma unroll
        for (int l = 0; l < NLAY; l++) {
            #pragma unroll
            for (int i = 0; i < 64; i++) acc[i] = 0.f;

            #pragma unroll
            for (int kq = 0; kq < 4; kq++) {
                const int g = l * 4 + kq;              // chunk index within tile
                __syncthreads();                       // refill target reads done
                issue_chunk(sb, SM_BB + (uint32_t)(((g + 1) & 1) * 32768),
                            tile_base + (size_t)((g + 1) & 15) * 32768, tid);
                cp_wait1();                            // chunk g landed; g+1 flying
                __syncthreads();                       // chunk g visible CTA-wide
                mma_chunk(sb, a_rel, a_xor, akoff, b_rel0, bkoff, b_xor,
                          SM_BB + (uint32_t)((g & 1) * 32768), kq, acc);
            }
            __syncthreads();   // all mma reads of A done before A rewrite

            if (l < NLAY - 1) {
                // epilogue: f16 bias + half2 softplus -> A (in place)
                const __half2* sbh2 = (const __half2*)(sm + SM_BIAS + l * 512);
                #pragma unroll
                for (int mf = 0; mf < 2; mf++) {
                    const int mlo = eml[mf];
                    const uint32_t alo = (uint32_t)(SM_A + (mlo >> 3) * 1024
                                                    + (mlo & 7) * 128);
                    const uint32_t xlo = (uint32_t)((mlo & 7) * 16);
                    #pragma unroll
                    for (int nf = 0; nf < 8; nf++) {
                        const int n0 = wn * 64 + nf * 8 + (ln & 3) * 2;
                        const __half2 b2 = sbh2[n0 >> 1];
                        const float* a4 = &acc[(mf * 8 + nf) * 4];
                        const uint32_t kt = (uint32_t)((n0 >> 6) * 8192)
                                          + ((uint32_t)((n0 & 63) * 2) ^ xlo);
                        __half2 v01 = __hadd2(__floats2half2_rn(a4[0], a4[1]), b2);
                        __half2 v23 = __hadd2(__floats2half2_rn(a4[2], a4[3]), b2);
                        *(__half2*)(sm + alo + kt)        = sp2p(v01);
                        *(__half2*)(sm + alo + 1024 + kt) = sp2p(v23);
                    }
                }
                // next chunk's top __syncthreads orders these writes before reads
            } else {
                // final layer: f32 poly softplus * Wout, fused 256->1 dot
                const __half* sbhh = (const __half*)(sm + SM_BIAS + (NLAY - 1) * 512);
                const float* wog = Wout + (size_t)s * HDIM;
                float rsum[4];
                #pragma unroll
                for (int mf = 0; mf < 2; mf++) {
                    float lo = 0.f, hi = 0.f;
                    #pragma unroll
                    for (int nf = 0; nf < 8; nf++) {
                        const int n0 = wn * 64 + nf * 8 + (ln & 3) * 2;
                        const float bv0 = __half2float(sbhh[n0]);
                        const float bv1 = __half2float(sbhh[n0 + 1]);
                        const float w0v = __ldg(wog + n0), w1v = __ldg(wog + n0 + 1);
                        const float* a4 = &acc[(mf * 8 + nf) * 4];
                        lo += softplus_poly(a4[0] + bv0) * w0v
                            + softplus_poly(a4[1] + bv1) * w1v;
                        hi += softplus_poly(a4[2] + bv0) * w0v
                            + softplus_poly(a4[3] + bv1) * w1v;
                    }
                    rsum[mf * 2] = lo; rsum[mf * 2 + 1] = hi;
                }
                #pragma unroll
                for (int i = 0; i < 4; i++) {
                    rsum[i] += __shfl_xor_sync(0xffffffffu, rsum[i], 1);
                    rsum[i] += __shfl_xor_sync(0xffffffffu, rsum[i], 2);
                }
                float* red = (float*)(sm + SM_RED);
                if ((ln & 3) == 0) {
                    #pragma unroll
                    for (int mf = 0; mf < 2; mf++) {
                        const int mloL = eml[mf] & 63;
                        red[wn * 64 + mloL]     = rsum[mf * 2];
                        red[wn * 64 + mloL + 8] = rsum[mf * 2 + 1];
                    }
                }
                __syncthreads();
                if (tid < 64 && base + tid < Ntot) {
                    float v = red[tid] + red[64 + tid] + red[128 + tid]
                            + red[192 + tid] + __ldg(bout + s);
                    out[(size_t)(base + tid) * NSER + s] = v;
                }
            }
        }
    }
    cp_wait0();   // drain the phantom prefetch before exit
}

extern "C" void kernel_launch(void* const* d_in, const int* in_sizes, int n_in,
                              void* d_out, int out_size) {
    const float* coords = (const float*)d_in[0];
    const float* W0     = (const float*)d_in[1];
    const float* b0     = (const float*)d_in[2];
    const float* Wh     = (const float*)d_in[3];
    const float* bh     = (const float*)d_in[4];
    const float* Wout   = (const float*)d_in[5];
    const float* bout   = (const float*)d_in[6];
    const int Npts = in_sizes[0] / 3;

    cudaFuncSetAttribute(mlp_kernel, cudaFuncAttributeMaxDynamicSharedMemorySize,
                         SMEM_BYTES);

    const int wtotal = NSER * NLAY * HDIM * HDIM;
    prep_weights<<<(wtotal + 255) / 256, 256>>>(Wh);

    int nsm = 148;
    cudaDeviceGetAttribute(&nsm, cudaDevAttrMultiProcessorCount, 0);
    int grid = (2 * nsm) & ~7;              // 2 CTAs/SM, multiple of 8
    if (grid < 8) grid = 8;
    const int nslots = grid / 8;
    const int ntiles = (Npts + TILE_M - 1) / TILE_M;

    mlp_kernel<<<grid, THREADS, SMEM_BYTES>>>(coords, W0, b0, bh, Wout, bout,
                                              (float*)d_out, Npts, ntiles, nslots);

    long long need = (long long)Npts * NSER + (long long)Npts * 3;
    if ((long long)out_size >= need) {
        cudaMemcpyAsync((float*)d_out + (size_t)Npts * NSER, coords,
                        sizeof(float) * (size_t)Npts * 3,
                        cudaMemcpyDeviceToDevice, 0);
    }
}

// round 17
// speedup vs baseline: 1.0284x; 1.0263x over previous
#include <cuda_runtime.h>
#include <cuda_fp16.h>
#include <cstdint>

#define NSER 8
#define NLAY 4
#define HDIM 256
#define TILE_M 64
#define THREADS 256

// ---- smem layout (byte offsets from 1024-aligned base) ----
#define SM_A      0                     // 64x256 fp16 SW128 blocked atoms (32768)
#define SM_BB     32768                 // B chunk double buffer: 2 x 32768
#define SM_BIAS   98304                 // ALL 4 layer biases as f16: 4 x 512
#define SM_W0     100352                // 3072 (f32)
#define SM_B0     103424                // 1024 (f32)
#define SM_RED    104448                // 256 floats (1024)
#define SM_CO     105472                // staged coords 64x3 f32 (768)
#define SMEM_BYTES (106240 + 1024)

// Pre-swizzled fp16 weight tiles: [s*4+l] tiles, each 256(out j) x 256(in k).
// Image = 16 contiguous 32KB chunks per series (4 per layer).
__device__ __half g_Bw[(size_t)NSER * NLAY * HDIM * HDIM];

__device__ __forceinline__ uint32_t swz(uint32_t o) { return o ^ ((o >> 3) & 0x70); }

__device__ __forceinline__ uint32_t b_off(int j, int k) {
    uint32_t o = ((uint32_t)(j >> 3) + (uint32_t)(k >> 6) * 32u) * 1024u
               + (uint32_t)(j & 7) * 128u + (uint32_t)(k & 63) * 2u;
    return swz(o);
}

__device__ __forceinline__ uint32_t s2u(const void* p) {
    uint32_t a;
    asm("{ .reg .u64 t; cvta.to.shared.u64 t, %1; cvt.u32.u64 %0, t; }" : "=r"(a) : "l"(p));
    return a;
}

// final-layer softplus: 1 MUFU (ex2) + f32 deg-5 poly for ln(1+u) (err<=1e-5)
__device__ __forceinline__ float softplus_poly(float x) {
    float u;
    asm("ex2.approx.ftz.f32 %0, %1;" : "=f"(u)
        : "f"(fabsf(x) * -1.4426950408889634f));
    float p = fmaf(0.03215845f, u, -0.13606275f);
    p = fmaf(p, u, 0.28947478f);
    p = fmaf(p, u, -0.49190896f);
    p = fmaf(p, u, 0.99949556f);
    return fmaxf(x, 0.f) + p * u;
}

// half2-native softplus (round-15 proven)
__device__ __forceinline__ __half2 sp2p(__half2 v) {
    const __half2 nL2E = __floats2half2_rn(-1.4426950408889634f,
                                           -1.4426950408889634f);
    __half2 t = __hmul2(__habs2(v), nL2E);
    __half2 u;
    asm("ex2.approx.f16x2 %0, %1;"
        : "=r"(*(uint32_t*)&u) : "r"(*(uint32_t*)&t));
    const __half2 c5 = __floats2half2_rn( 0.03215845f,  0.03215845f);
    const __half2 c4 = __floats2half2_rn(-0.13606275f, -0.13606275f);
    const __half2 c3 = __floats2half2_rn( 0.28947478f,  0.28947478f);
    const __half2 c2 = __floats2half2_rn(-0.49190896f, -0.49190896f);
    const __half2 c1 = __floats2half2_rn( 0.99949556f,  0.99949556f);
    __half2 p = __hfma2(c5, u, c4);
    p = __hfma2(p, u, c3);
    p = __hfma2(p, u, c2);
    p = __hfma2(p, u, c1);
    __half2 relu = __hmax2(v, __floats2half2_rn(0.f, 0.f));
    return __hfma2(p, u, relu);
}

// ---- prep: fp32 Wh[s][l][k][j] (k=in, j=out) -> fp16 pre-swizzled B images ----
__global__ void prep_weights(const float* __restrict__ Wh) {
    int idx = blockIdx.x * blockDim.x + threadIdx.x;
    if (idx >= NSER * NLAY * HDIM * HDIM) return;
    int t = idx >> 16;
    int r = idx & 0xFFFF;
    int k = r >> 8;
    int j = r & 0xFF;
    float w = Wh[((size_t)t << 16) + (k << 8) + j];
    char* base = (char*)g_Bw + (size_t)t * 131072;
    *(__half*)(base + b_off(j, k)) = __float2half_rn(w);
}

__device__ __forceinline__ void ldsm_x4(uint32_t& r0, uint32_t& r1, uint32_t& r2,
                                        uint32_t& r3, uint32_t a) {
    asm volatile("ldmatrix.sync.aligned.m8n8.x4.shared.b16 {%0,%1,%2,%3}, [%4];"
                 : "=r"(r0), "=r"(r1), "=r"(r2), "=r"(r3) : "r"(a));
}
__device__ __forceinline__ void mma16816(float* c, uint32_t a0, uint32_t a1,
                                         uint32_t a2, uint32_t a3,
                                         uint32_t b0, uint32_t b1) {
    asm volatile(
        "mma.sync.aligned.m16n8k16.row.col.f32.f16.f16.f32 "
        "{%0,%1,%2,%3}, {%4,%5,%6,%7}, {%8,%9}, {%0,%1,%2,%3};"
        : "+f"(c[0]), "+f"(c[1]), "+f"(c[2]), "+f"(c[3])
        : "r"(a0), "r"(a1), "r"(a2), "r"(a3), "r"(b0), "r"(b1));
}

__device__ __forceinline__ void cp16(uint32_t saddr, const void* g) {
    asm volatile("cp.async.cg.shared.global [%0], [%1], 16;"
                 :: "r"(saddr), "l"(g) : "memory");
}
__device__ __forceinline__ void cp_commit() {
    asm volatile("cp.async.commit_group;" ::: "memory");
}
__device__ __forceinline__ void cp_wait0() {
    asm volatile("cp.async.wait_group 0;" ::: "memory");
}

// copy one 32KB chunk (64 k-cols of B) by 256 threads: 8 x 16B per thread
__device__ __forceinline__ void issue_chunk(uint32_t sb, uint32_t bufoff,
                                            const char* g, int tid) {
    uint32_t d = sb + bufoff + (uint32_t)tid * 16u;
    #pragma unroll
    for (int i = 0; i < 8; i++)
        cp16(d + (uint32_t)i * 4096u, g + (size_t)tid * 16 + (size_t)i * 4096);
    cp_commit();
}

// one quarter-k of the layer MMA, software-pipelined (round-16 form):
// B fragments double-buffered across nf2; A fragments across kss.
__device__ __forceinline__ void mma_chunk(uint32_t sb, const uint32_t* a_rel,
    uint32_t a_xor, int akoff, uint32_t b_rel0, int bkoff, uint32_t b_xor,
    uint32_t bufoff, int kq, float* acc)
{
    uint32_t af[2][8];
    uint32_t br[2][4];

    // preload A for kss=0
    {
        const int ka = kq * 64 + akoff;
        const uint32_t aterm = (uint32_t)((ka >> 6) * 8192)
                             + ((uint32_t)((ka & 63) * 2) ^ a_xor);
        ldsm_x4(af[0][0], af[0][1], af[0][2], af[0][3], sb + a_rel[0] + aterm);
        ldsm_x4(af[0][4], af[0][5], af[0][6], af[0][7], sb + a_rel[1] + aterm);
    }

    #pragma unroll
    for (int kss = 0; kss < 4; kss++) {
        const int cur = kss & 1, nxt = cur ^ 1;
        const int kb = kss * 16 + bkoff;               // chunk-local k (<64)
        uint32_t baddr = sb + bufoff + b_rel0
                       + ((uint32_t)(kb * 2) ^ b_xor);
        // preload B for nf2=0
        ldsm_x4(br[0][0], br[0][1], br[0][2], br[0][3], baddr);

        #pragma unroll
        for (int nf2 = 0; nf2 < 4; nf2++) {
            const int bc = nf2 & 1;
            if (nf2 < 3) {
                // prefetch next B quartet
                ldsm_x4(br[bc ^ 1][0], br[bc ^ 1][1], br[bc ^ 1][2],
                        br[bc ^ 1][3], baddr + 2048);
            } else if (kss < 3) {
                // prefetch next kss's A fragments
                const int ka = kq * 64 + (kss + 1) * 16 + akoff;
                const uint32_t aterm = (uint32_t)((ka >> 6) * 8192)
                                     + ((uint32_t)((ka & 63) * 2) ^ a_xor);
                ldsm_x4(af[nxt][0], af[nxt][1], af[nxt][2], af[nxt][3],
                        sb + a_rel[0] + aterm);
                ldsm_x4(af[nxt][4], af[nxt][5], af[nxt][6], af[nxt][7],
                        sb + a_rel[1] + aterm);
            }
            mma16816(&acc[(nf2 * 2) * 4],
                     af[cur][0], af[cur][1], af[cur][2], af[cur][3],
                     br[bc][0], br[bc][1]);
            mma16816(&acc[(nf2 * 2 + 1) * 4],
                     af[cur][0], af[cur][1], af[cur][2], af[cur][3],
                     br[bc][2], br[bc][3]);
            mma16816(&acc[(8 + nf2 * 2) * 4],
                     af[cur][4], af[cur][5], af[cur][6], af[cur][7],
                     br[bc][0], br[bc][1]);
            mma16816(&acc[(8 + nf2 * 2 + 1) * 4],
                     af[cur][4], af[cur][5], af[cur][6], af[cur][7],
                     br[bc][2], br[bc][3]);
            baddr += 2048;
        }
    }
}

__global__ void __launch_bounds__(THREADS, 2)
mlp_kernel(const float* __restrict__ coords,
           const float* __restrict__ W0,
           const float* __restrict__ b0,
           const float* __restrict__ bh,
           const float* __restrict__ Wout,
           const float* __restrict__ bout,
           float* __restrict__ out,
           int Ntot, int ntiles, int nslots)
{
    extern __shared__ char smem_raw[];
    char* sm = (char*)(((uintptr_t)smem_raw + 1023) & ~(uintptr_t)1023);
    const uint32_t sb = s2u(sm);
    const int tid = threadIdx.x;
    const int s    = blockIdx.x & 7;        // series pinned to this CTA
    const int slot = blockIdx.x >> 3;       // tile-stride slot

    const int wid = tid >> 5, ln = tid & 31;
    const int wm = wid & 1;                 // 2 M-tiles of 32 rows
    const int wn = wid >> 1;                // 4 N-tiles of 64 cols

    const char* tile_base = (const char*)(g_Bw + ((size_t)(s * NLAY) << 16));

    // ---- one-time prologue: chunk 0 + stage W0/b0 + biases (as f16) ----
    issue_chunk(sb, SM_BB, tile_base, tid);
    {
        const float* w0g = W0 + (size_t)s * 3 * HDIM;
        #pragma unroll
        for (int i = tid; i < 3 * HDIM; i += THREADS)
            ((float*)(sm + SM_W0))[i] = w0g[i];
        ((float*)(sm + SM_B0))[tid] = b0[(size_t)s * HDIM + tid];
        #pragma unroll
        for (int lj = 0; lj < NLAY; lj++)
            ((__half*)(sm + SM_BIAS + lj * 512))[tid] =
                __float2half_rn(bh[(size_t)(s * NLAY + lj) * HDIM + tid]);
    }

    // ---- per-lane fragment addressing (proven forms) ----
    uint32_t a_rel[2];
    #pragma unroll
    for (int mf = 0; mf < 2; mf++) {
        int m = wm * 32 + mf * 16 + (ln & 15);
        a_rel[mf] = (uint32_t)(SM_A + (m >> 3) * 1024 + (m & 7) * 128);
    }
    const uint32_t a_xor = (uint32_t)((ln & 7) * 16);
    const int akoff = (ln & 16) ? 8 : 0;
    const uint32_t b_rel0 = (uint32_t)(wn * 8192 + (ln & 7) * 128
                                       + ((ln & 16) ? 1024 : 0));
    const uint32_t b_xor = (uint32_t)((ln & 7) * 16);
    const int bkoff = (ln & 8) ? 8 : 0;

    const int eml[2] = { wm * 32 + 0 * 16 + (ln >> 2),
                         wm * 32 + 1 * 16 + (ln >> 2) };

    // layer-0 lane constants: thread = 8 rows (tr) x 8 cols (tj)
    const int tj = tid & 31;                 // col group: j = tj*8 .. tj*8+7
    const int tr = tid >> 5;                 // row group: m = tr*8 .. tr*8+7
    const uint32_t a0base = (uint32_t)(tr * 1024 + (tj >> 3) * 8192);
    const uint32_t jlow2 = (uint32_t)(((tj & 7) * 8) * 2);  // (j&63)*2 for c=0

    __syncthreads();   // staging visible (chunk 0 still in flight)

    for (int t = slot; t < ntiles; t += nslots) {
        const int base = t * TILE_M;

        // ---- stage coords for this tile (64 rows x 3 f32) ----
        if (tid < 192) {
            size_t gi = (size_t)base * 3 + tid;
            ((float*)(sm + SM_CO))[tid] =
                (gi < (size_t)Ntot * 3) ? coords[gi] : 0.f;
        }
        __syncthreads();

        // ---- layer 0: regs-resident W0 slice; 8 rows x 8 cols per thread ----
        {
            const float* sw0 = (const float*)(sm + SM_W0);
            const float* sb0 = (const float*)(sm + SM_B0);
            const float* co  = (const float*)(sm + SM_CO);
            const int j0 = tj * 8;
            float4 wa0 = *(const float4*)(sw0 + j0);
            float4 wa1 = *(const float4*)(sw0 + j0 + 4);
            float4 wb0 = *(const float4*)(sw0 + 256 + j0);
            float4 wb1 = *(const float4*)(sw0 + 256 + j0 + 4);
            float4 wc0 = *(const float4*)(sw0 + 512 + j0);
            float4 wc1 = *(const float4*)(sw0 + 512 + j0 + 4);
            float4 bb0 = *(const float4*)(sb0 + j0);
            float4 bb1 = *(const float4*)(sb0 + j0 + 4);
            const float wa[8] = {wa0.x,wa0.y,wa0.z,wa0.w,wa1.x,wa1.y,wa1.z,wa1.w};
            const float wb[8] = {wb0.x,wb0.y,wb0.z,wb0.w,wb1.x,wb1.y,wb1.z,wb1.w};
            const float wc[8] = {wc0.x,wc0.y,wc0.z,wc0.w,wc1.x,wc1.y,wc1.z,wc1.w};
            const float bv[8] = {bb0.x,bb0.y,bb0.z,bb0.w,bb1.x,bb1.y,bb1.z,bb1.w};
            #pragma unroll
            for (int r = 0; r < 8; r++) {
                const int m = tr * 8 + r;
                const float c0 = co[m * 3], c1 = co[m * 3 + 1], c2 = co[m * 3 + 2];
                const uint32_t rowrel = a0base + (uint32_t)(r * 128);
                const uint32_t rxor = (uint32_t)(r * 16);
                #pragma unroll
                for (int c = 0; c < 8; c += 2) {
                    float v0 = bv[c]   + c0 * wa[c]   + c1 * wb[c]   + c2 * wc[c];
                    float v1 = bv[c+1] + c0 * wa[c+1] + c1 * wb[c+1] + c2 * wc[c+1];
                    uint32_t rel = rowrel + ((jlow2 + (uint32_t)(c * 2)) ^ rxor);
                    *(__half2*)(sm + SM_A + rel) = sp2p(__floats2half2_rn(v0, v1));
                }
            }
        }

        float acc[64];

        #pragma unroll
        for (int l = 0; l < NLAY; l++) {
            #pragma unroll
            for (int i = 0; i < 64; i++) acc[i] = 0.f;

            #pragma unroll
            for (int kq = 0; kq < 4; kq++) {
                const int g = l * 4 + kq;              // chunk index within tile
                cp_wait0();                            // chunk g landed (sole group)
                __syncthreads();                       // visibility + all reads of
                                                       // buf[(g+1)&1] (mma g-1) done
                issue_chunk(sb, SM_BB + (uint32_t)(((g + 1) & 1) * 32768),
                            tile_base + (size_t)((g + 1) & 15) * 32768, tid);
                mma_chunk(sb, a_rel, a_xor, akoff, b_rel0, bkoff, b_xor,
                          SM_BB + (uint32_t)((g & 1) * 32768), kq, acc);
            }
            __syncthreads();   // all mma reads of A done before A rewrite

            if (l < NLAY - 1) {
                // epilogue: f16 bias + half2 softplus -> A (in place);
                // overlaps the in-flight refill of the next chunk
                const __half2* sbh2 = (const __half2*)(sm + SM_BIAS + l * 512);
                #pragma unroll
                for (int mf = 0; mf < 2; mf++) {
                    const int mlo = eml[mf];
                    const uint32_t alo = (uint32_t)(SM_A + (mlo >> 3) * 1024
                                                    + (mlo & 7) * 128);
                    const uint32_t xlo = (uint32_t)((mlo & 7) * 16);
                    #pragma unroll
                    for (int nf = 0; nf < 8; nf++) {
                        const int n0 = wn * 64 + nf * 8 + (ln & 3) * 2;
                        const __half2 b2 = sbh2[n0 >> 1];
                        const float* a4 = &acc[(mf * 8 + nf) * 4];
                        const uint32_t kt = (uint32_t)((n0 >> 6) * 8192)
                                          + ((uint32_t)((n0 & 63) * 2) ^ xlo);
                        __half2 v01 = __hadd2(__floats2half2_rn(a4[0], a4[1]), b2);
                        __half2 v23 = __hadd2(__floats2half2_rn(a4[2], a4[3]), b2);
                        *(__half2*)(sm + alo + kt)        = sp2p(v01);
                        *(__half2*)(sm + alo + 1024 + kt) = sp2p(v23);
                    }
                }
                // next chunk's top __syncthreads orders these writes before reads
            } else {
                // final layer: f32 poly softplus * Wout, fused 256->1 dot
                const __half* sbhh = (const __half*)(sm + SM_BIAS + (NLAY - 1) * 512);
                const float* wog = Wout + (size_t)s * HDIM;
                float rsum[4];
                #pragma unroll
                for (int mf = 0; mf < 2; mf++) {
                    float lo = 0.f, hi = 0.f;
                    #pragma unroll
                    for (int nf = 0; nf < 8; nf++) {
                        const int n0 = wn * 64 + nf * 8 + (ln & 3) * 2;
                        const float bv0 = __half2float(sbhh[n0]);
                        const float bv1 = __half2float(sbhh[n0 + 1]);
                        const float w0v = __ldg(wog + n0), w1v = __ldg(wog + n0 + 1);
                        const float* a4 = &acc[(mf * 8 + nf) * 4];
                        lo += softplus_poly(a4[0] + bv0) * w0v
                            + softplus_poly(a4[1] + bv1) * w1v;
                        hi += softplus_poly(a4[2] + bv0) * w0v
                            + softplus_poly(a4[3] + bv1) * w1v;
                    }
                    rsum[mf * 2] = lo; rsum[mf * 2 + 1] = hi;
                }
                #pragma unroll
                for (int i = 0; i < 4; i++) {
                    rsum[i] += __shfl_xor_sync(0xffffffffu, rsum[i], 1);
                    rsum[i] += __shfl_xor_sync(0xffffffffu, rsum[i], 2);
                }
                float* red = (float*)(sm + SM_RED);
                if ((ln & 3) == 0) {
                    #pragma unroll
                    for (int mf = 0; mf < 2; mf++) {
                        const int mloL = eml[mf] & 63;
                        red[wn * 64 + mloL]     = rsum[mf * 2];
                        red[wn * 64 + mloL + 8] = rsum[mf * 2 + 1];
                    }
                }
                __syncthreads();
                if (tid < 64 && base + tid < Ntot) {
                    float v = red[tid] + red[64 + tid] + red[128 + tid]
                            + red[192 + tid] + __ldg(bout + s);
                    out[(size_t)(base + tid) * NSER + s] = v;
                }
            }
        }
    }
    cp_wait0();   // drain the phantom prefetch before exit
}

extern "C" void kernel_launch(void* const* d_in, const int* in_sizes, int n_in,
                              void* d_out, int out_size) {
    const float* coords = (const float*)d_in[0];
    const float* W0     = (const float*)d_in[1];
    const float* b0     = (const float*)d_in[2];
    const float* Wh     = (const float*)d_in[3];
    const float* bh     = (const float*)d_in[4];
    const float* Wout   = (const float*)d_in[5];
    const float* bout   = (const float*)d_in[6];
    const int Npts = in_sizes[0] / 3;

    cudaFuncSetAttribute(mlp_kernel, cudaFuncAttributeMaxDynamicSharedMemorySize,
                         SMEM_BYTES);

    const int wtotal = NSER * NLAY * HDIM * HDIM;
    prep_weights<<<(wtotal + 255) / 256, 256>>>(Wh);

    int nsm = 148;
    cudaDeviceGetAttribute(&nsm, cudaDevAttrMultiProcessorCount, 0);
    int grid = (2 * nsm) & ~7;              // 2 CTAs/SM, multiple of 8
    if (grid < 8) grid = 8;
    const int nslots = grid / 8;
    const int ntiles = (Npts + TILE_M - 1) / TILE_M;

    mlp_kernel<<<grid, THREADS, SMEM_BYTES>>>(coords, W0, b0, bh, Wout, bout,
                                              (float*)d_out, Npts, ntiles, nslots);

    long long need = (long long)Npts * NSER + (long long)Npts * 3;
    if ((long long)out_size >= need) {
        cudaMemcpyAsync((float*)d_out + (size_t)Npts * NSER, coords,
                        sizeof(float) * (size_t)Npts * 3,
                        cudaMemcpyDeviceToDevice, 0);
    }
}